// round 6
// baseline (speedup 1.0000x reference)
#include <cuda_runtime.h>
#include <cuda_bf16.h>
#include <cstdint>

// ---------------------------------------------------------------------------
// Problem constants
// ---------------------------------------------------------------------------
#define OUTF   4096
#define INF    4096
#define NBATCH 4096

// Device-global scratch (allocation-guard safe).
__device__ float         g_W [(size_t)OUTF  * INF];   // 64 MB scattered dense weights
__device__ __nv_bfloat16 g_Ah[(size_t)NBATCH * INF];  // 32 MB X hi
__device__ __nv_bfloat16 g_Al[(size_t)NBATCH * INF];  // 32 MB X lo
__device__ __nv_bfloat16 g_Bh[(size_t)OUTF  * INF];   // 32 MB W hi
__device__ __nv_bfloat16 g_Bl[(size_t)OUTF  * INF];   // 32 MB W lo

// ---------------------------------------------------------------------------
// PTX helpers (sm_80-level features only: cp.async, ldmatrix, mma.sync)
// ---------------------------------------------------------------------------
__device__ __forceinline__ uint32_t smem_u32(const void* p) {
    uint32_t a;
    asm("{ .reg .u64 t; cvta.to.shared.u64 t, %1; cvt.u32.u64 %0, t; }"
        : "=r"(a) : "l"(p));
    return a;
}

__device__ __forceinline__ void cpa16(uint32_t dst, const void* src) {
    asm volatile("cp.async.cg.shared.global [%0], [%1], 16;"
                 :: "r"(dst), "l"(__cvta_generic_to_global(src)));
}
#define CP_COMMIT() asm volatile("cp.async.commit_group;" ::: "memory")
#define CP_WAIT1()  asm volatile("cp.async.wait_group 1;" ::: "memory")

__device__ __forceinline__ void ldsm4(uint32_t* r, uint32_t addr) {
    asm volatile("ldmatrix.sync.aligned.m8n8.x4.shared.b16 {%0,%1,%2,%3}, [%4];"
                 : "=r"(r[0]), "=r"(r[1]), "=r"(r[2]), "=r"(r[3]) : "r"(addr));
}

__device__ __forceinline__ void mma16816(float* d, const uint32_t* a,
                                         const uint32_t* b) {
    asm volatile(
        "mma.sync.aligned.m16n8k16.row.col.f32.bf16.bf16.f32 "
        "{%0,%1,%2,%3}, {%4,%5,%6,%7}, {%8,%9}, {%0,%1,%2,%3};"
        : "+f"(d[0]), "+f"(d[1]), "+f"(d[2]), "+f"(d[3])
        : "r"(a[0]), "r"(a[1]), "r"(a[2]), "r"(a[3]), "r"(b[0]), "r"(b[1]));
}

// ---------------------------------------------------------------------------
// Pre-kernels: zero W, scatter COO, hi/lo bf16 split of X and W
// ---------------------------------------------------------------------------
__global__ void zero_W_kernel() {
    size_t n4 = (size_t)OUTF * INF / 4;
    float4* p = reinterpret_cast<float4*>(g_W);
    float4 z = make_float4(0.f, 0.f, 0.f, 0.f);
    for (size_t i = (size_t)blockIdx.x * blockDim.x + threadIdx.x; i < n4;
         i += (size_t)gridDim.x * blockDim.x)
        p[i] = z;
}

__global__ void scatter_W_kernel(const float* __restrict__ w,
                                 const int* __restrict__ rows,
                                 const int* __restrict__ cols, int nnz) {
    int i = blockIdx.x * blockDim.x + threadIdx.x;
    int stride = gridDim.x * blockDim.x;
    for (; i < nnz; i += stride)
        atomicAdd(&g_W[(size_t)rows[i] * INF + cols[i]], w[i]);
}

__device__ __forceinline__ void split_body(const float* __restrict__ src,
                                           __nv_bfloat16* __restrict__ dh,
                                           __nv_bfloat16* __restrict__ dl) {
    size_t n4 = (size_t)INF * NBATCH / 4;
    for (size_t i = (size_t)blockIdx.x * blockDim.x + threadIdx.x; i < n4;
         i += (size_t)gridDim.x * blockDim.x) {
        float4 v = reinterpret_cast<const float4*>(src)[i];
        __nv_bfloat16 h0 = __float2bfloat16_rn(v.x);
        __nv_bfloat16 h1 = __float2bfloat16_rn(v.y);
        __nv_bfloat16 h2 = __float2bfloat16_rn(v.z);
        __nv_bfloat16 h3 = __float2bfloat16_rn(v.w);
        __nv_bfloat16 l0 = __float2bfloat16_rn(v.x - __bfloat162float(h0));
        __nv_bfloat16 l1 = __float2bfloat16_rn(v.y - __bfloat162float(h1));
        __nv_bfloat16 l2 = __float2bfloat16_rn(v.z - __bfloat162float(h2));
        __nv_bfloat16 l3 = __float2bfloat16_rn(v.w - __bfloat162float(h3));
        reinterpret_cast<__nv_bfloat162*>(dh)[i * 2 + 0] = __halves2bfloat162(h0, h1);
        reinterpret_cast<__nv_bfloat162*>(dh)[i * 2 + 1] = __halves2bfloat162(h2, h3);
        reinterpret_cast<__nv_bfloat162*>(dl)[i * 2 + 0] = __halves2bfloat162(l0, l1);
        reinterpret_cast<__nv_bfloat162*>(dl)[i * 2 + 1] = __halves2bfloat162(l2, l3);
    }
}
__global__ void split_x_kernel(const float* __restrict__ x) { split_body(x, g_Ah, g_Al); }
__global__ void split_w_kernel() { split_body(g_W, g_Bh, g_Bl); }

// ---------------------------------------------------------------------------
// bf16x3 HMMA GEMM: Y = X.W^T + bias
// CTA 256x128, BK=32, 2-stage cp.async pipeline, 16 warps (4x4), warp 64x32.
// ---------------------------------------------------------------------------
#define BM 256
#define BN 128
#define BK 32
#define NIT (INF / BK)          // 128
#define ROWB 80                 // 64B data + 16B pad: conflict-free ldmatrix
#define A_TILEB (BM * ROWB)     // 20480
#define B_TILEB (BN * ROWB)     // 10240
#define OFF_AL  A_TILEB                     // 20480
#define OFF_BH  (2 * A_TILEB)               // 40960
#define OFF_BL  (2 * A_TILEB + B_TILEB)     // 51200
#define STAGEB  (2 * A_TILEB + 2 * B_TILEB) // 61440
#define SMEMB   (2 * STAGEB)                // 122880

__device__ __forceinline__ void load_stage(uint32_t sb, int stage, int kblk,
                                           int bm, int bn, int tid) {
    const uint32_t base = sb + stage * STAGEB;
    const int k0 = kblk * BK;
    // A tiles: 256 rows x 4 float4 = 1024 chunks (2 per thread)
#pragma unroll
    for (int j = 0; j < 2; j++) {
        int idx = tid + j * 512;
        int r   = idx >> 2;          // 0..255
        int ce  = (idx & 3) * 8;     // element col
        int cb  = (idx & 3) * 16;    // byte col
        uint32_t drow = base + r * ROWB + cb;
        const size_t arow = (size_t)(bm + r) * INF + k0 + ce;
        cpa16(drow,          g_Ah + arow);
        cpa16(drow + OFF_AL, g_Al + arow);
    }
    // B tiles: 128 rows x 4 float4 = 512 chunks (1 per thread)
    {
        int r  = tid >> 2;           // 0..127
        int ce = (tid & 3) * 8;
        int cb = (tid & 3) * 16;
        uint32_t drow = base + r * ROWB + cb;
        const size_t brow = (size_t)(bn + r) * INF + k0 + ce;
        cpa16(drow + OFF_BH, g_Bh + brow);
        cpa16(drow + OFF_BL, g_Bl + brow);
    }
}

__global__ __launch_bounds__(512, 1)
void gemm_bf16x3(const float* __restrict__ bias, float* __restrict__ Y) {
    extern __shared__ char smem[];
    const uint32_t sb = smem_u32(smem);

    const int tid  = threadIdx.x;
    const int lane = tid & 31;
    const int wid  = tid >> 5;
    const int wm   = wid & 3;        // 0..3 -> 64-row slab
    const int wn   = wid >> 2;       // 0..3 -> 32-col slab
    const int bm   = blockIdx.y * BM;
    const int bn   = blockIdx.x * BN;

    // ldmatrix per-lane address offsets (within a tile) — mappings carried
    // over verbatim from the verified 128x128 kernel.
    const uint32_t aRow = (uint32_t)(wm * 64 + (lane & 15)) * ROWB + ((lane >> 4) << 4);
    const uint32_t bRow = (uint32_t)(wn * 32 + ((lane >> 4) << 3) + (lane & 7)) * ROWB
                        + (((lane >> 3) & 1) << 4);

    float acc[4][4][4] = {};

    load_stage(sb, 0, 0, bm, bn, tid);
    CP_COMMIT();

#pragma unroll 1
    for (int it = 0; it < NIT; it++) {
        const int ld = it + 1;
        if (ld < NIT) load_stage(sb, ld & 1, ld, bm, bn, tid);
        CP_COMMIT();
        CP_WAIT1();                  // all but newest group done -> stage it ready
        __syncthreads();

        const uint32_t base = sb + (it & 1) * STAGEB;
#pragma unroll
        for (int ks = 0; ks < 2; ks++) {
            const uint32_t kb = ks * 32;   // 16 elements = 32 bytes
            uint32_t aH[4][4], aL[4][4], bH[2][4], bL[2][4];
#pragma unroll
            for (int mt = 0; mt < 4; mt++) {
                ldsm4(aH[mt], base + aRow + mt * 16 * ROWB + kb);
                ldsm4(aL[mt], base + OFF_AL + aRow + mt * 16 * ROWB + kb);
            }
#pragma unroll
            for (int nt2 = 0; nt2 < 2; nt2++) {
                ldsm4(bH[nt2], base + OFF_BH + bRow + nt2 * 16 * ROWB + kb);
                ldsm4(bL[nt2], base + OFF_BL + bRow + nt2 * 16 * ROWB + kb);
            }
#pragma unroll
            for (int mt = 0; mt < 4; mt++)
#pragma unroll
                for (int nt = 0; nt < 4; nt++) {
                    const uint32_t* bh = &bH[nt >> 1][(nt & 1) * 2];
                    const uint32_t* bl = &bL[nt >> 1][(nt & 1) * 2];
                    mma16816(acc[mt][nt], aH[mt], bh);
                    mma16816(acc[mt][nt], aH[mt], bl);
                    mma16816(acc[mt][nt], aL[mt], bh);
                }
        }
        __syncthreads();             // stage (it&1) free for reuse next iter
    }

    // Epilogue: bias + store.
#pragma unroll
    for (int mt = 0; mt < 4; mt++) {
        const int r0 = bm + wm * 64 + mt * 16 + (lane >> 2);
#pragma unroll
        for (int nt = 0; nt < 4; nt++) {
            const int c = bn + wn * 32 + nt * 8 + (lane & 3) * 2;
            const float2 bv = *reinterpret_cast<const float2*>(&bias[c]);
            float2 v0, v1;
            v0.x = acc[mt][nt][0] + bv.x;
            v0.y = acc[mt][nt][1] + bv.y;
            v1.x = acc[mt][nt][2] + bv.x;
            v1.y = acc[mt][nt][3] + bv.y;
            *reinterpret_cast<float2*>(&Y[(size_t)r0 * OUTF + c])       = v0;
            *reinterpret_cast<float2*>(&Y[(size_t)(r0 + 8) * OUTF + c]) = v1;
        }
    }
}

// ---------------------------------------------------------------------------
// Launch
// ---------------------------------------------------------------------------
extern "C" void kernel_launch(void* const* d_in, const int* in_sizes, int n_in,
                              void* d_out, int out_size) {
    const float* x     = (const float*)d_in[0];
    const float* wvals = (const float*)d_in[1];
    const float* bias  = (const float*)d_in[2];
    const int*   rows  = (const int*)d_in[3];
    const int*   cols  = (const int*)d_in[4];
    float*       out   = (float*)d_out;
    const int    nnz   = in_sizes[1];

    cudaFuncSetAttribute(gemm_bf16x3, cudaFuncAttributeMaxDynamicSharedMemorySize,
                         SMEMB);

    zero_W_kernel<<<2048, 256>>>();
    scatter_W_kernel<<<(nnz + 255) / 256, 256>>>(wvals, rows, cols, nnz);
    split_x_kernel<<<4096, 256>>>(x);
    split_w_kernel<<<4096, 256>>>();

    dim3 grid(OUTF / BN, NBATCH / BM);   // (32, 16)
    gemm_bf16x3<<<grid, 512, SMEMB>>>(bias, out);
}